// round 6
// baseline (speedup 1.0000x reference)
#include <cuda_runtime.h>
#include <cstdint>

#define NN    128
#define BATCH 2
#define LSEQ  2048
#define CL    32
#define PCH   (LSEQ/CL)   // 64 chunks per batch

// ---------------- device scratch (no allocations allowed) ----------------
__device__ float4 g_Ad4v[32*NN];                  // Ad in [m/4][n][4] layout (float4 per (j,n))
__device__ float  g_Ad[NN*NN];                    // Ad row-major
__device__ float  g_AT[NN*NN];                    // A transposed
__device__ float  g_Bd[NN];
__device__ float  g_pbuf[2][NN*NN];               // ping-pong for matrix squaring
__device__ float4 g_M324v[32*NN];                 // Ad^32 in [m/4][n][4] layout
__device__ float4 g_state4[BATCH*LSEQ*(NN/4)];    // states (2 MB, L2-resident)
__device__ float  g_carry[BATCH*PCH*NN];

// ---------------- setup: transpose A ----------------
__global__ void k_transpose(const float* __restrict__ A) {
    int i = blockIdx.x, j = threadIdx.x;
    g_AT[j*NN + i] = A[i*NN + j];
}

// ---------------- setup: GBT discretization via forward substitution -----
// P1 = I - 0.5*A is LOWER TRIANGULAR (HiPPO-LegS A is lower triangular).
// Block j solves column j of: P1 * Ad = I + 0.5*A  (j<128), P1 * Bd = B (j==128).
// Thread i owns row i; double precision; one __syncthreads per step
// (double-buffered broadcast slot makes a single barrier sufficient).
__global__ __launch_bounds__(NN) void k_solve(const float* __restrict__ A,
                                              const float* __restrict__ Bv) {
    int j = blockIdx.x, i = threadIdx.x;
    __shared__ double sh[2];
    double x;
    if (j < NN) x = (i == j ? 1.0 : 0.0) + 0.5 * (double)A[i*NN + j];
    else        x = (double)Bv[i];

    float at_cur = g_AT[i];  // A[i][0]
    for (int k = 0; k < NN; k++) {
        double p1 = (i == k ? 1.0 : 0.0) - 0.5 * (double)at_cur;  // P1[i][k]
        if (i == k) sh[k & 1] = x / p1;
        float at_next = (k < NN-1) ? g_AT[(k+1)*NN + i] : 0.f;
        __syncthreads();
        double xk = sh[k & 1];
        if (i == k)      x = xk;
        else if (i > k)  x -= p1 * xk;
        at_cur = at_next;
    }
    float xf = (float)x;
    if (j < NN) {
        g_Ad[i*NN + j] = xf;
        ((float*)g_Ad4v)[(j >> 2)*512 + (i << 2) + (j & 3)] = xf;
    } else {
        g_Bd[i] = xf;
    }
}

// ---------------- setup: matrix squaring (Ad^2 ... Ad^32) ----------------
__global__ void k_square(int s) {
    const float* __restrict__ in  = (s == 0) ? g_Ad : g_pbuf[(s-1) & 1];
    float* __restrict__ out = g_pbuf[s & 1];
    int r = blockIdx.x, c = threadIdx.x;
    __shared__ float row[NN];
    row[c] = in[r*NN + c];
    __syncthreads();
    float a0 = 0.f, a1 = 0.f, a2 = 0.f, a3 = 0.f;
    #pragma unroll
    for (int m = 0; m < NN; m += 4) {
        a0 += row[m]   * in[(m  )*NN + c];
        a1 += row[m+1] * in[(m+1)*NN + c];
        a2 += row[m+2] * in[(m+2)*NN + c];
        a3 += row[m+3] * in[(m+3)*NN + c];
    }
    float acc = (a0 + a1) + (a2 + a3);
    out[r*NN + c] = acc;
    if (s == 4)  // final = Ad^32: also emit [m/4][n][4] layout for carry kernel
        ((float*)g_M324v)[(c >> 2)*512 + (r << 2) + (c & 3)] = acc;
}

// ---------------- phase A: per-chunk local scan from zero state ----------
__global__ __launch_bounds__(NN, 1) void k_local(const float* __restrict__ f) {
    int b = blockIdx.x >> 6, p = blockIdx.x & 63;
    int n = threadIdx.x;
    __shared__ float4 cbuf[2][NN/4];
    __shared__ float  fs[CL];
    float4 row[32];
    #pragma unroll
    for (int j = 0; j < 32; j++) row[j] = g_Ad4v[j*NN + n];  // Ad row n, coalesced
    float bd = g_Bd[n];
    if (n < CL) fs[n] = f[b*LSEQ + p*CL + n];
    ((float*)cbuf[0])[n] = 0.f;
    __syncthreads();

    float* gs = (float*)g_state4 + (size_t)(b*LSEQ + p*CL)*NN + n;
    int cur = 0;
    #pragma unroll 1
    for (int i = 0; i < CL; i++) {
        float a0 = 0.f, a1 = 0.f, a2 = 0.f, a3 = 0.f;
        #pragma unroll
        for (int j = 0; j < 32; j++) {
            float4 c4 = cbuf[cur][j];
            a0 += row[j].x * c4.x;  a1 += row[j].y * c4.y;
            a2 += row[j].z * c4.z;  a3 += row[j].w * c4.w;
        }
        float v = (a0 + a1) + (a2 + a3) + bd * fs[i];
        ((float*)cbuf[cur ^ 1])[n] = v;
        gs[(size_t)i * NN] = v;
        cur ^= 1;
        __syncthreads();
    }
}

// ---------------- phase B: serial carry chain with Ad^32 -----------------
// carry_0 = 0 ; carry_p = Ad^32 * carry_{p-1} + local_end_{p-1}
__global__ __launch_bounds__(NN, 1) void k_carry() {
    int b = blockIdx.x;
    int n = threadIdx.x;
    __shared__ float4 cbuf[2][NN/4];
    float4 row[32];
    #pragma unroll
    for (int j = 0; j < 32; j++) row[j] = g_M324v[j*NN + n];
    ((float*)cbuf[0])[n] = 0.f;
    g_carry[(b*PCH + 0)*NN + n] = 0.f;
    __syncthreads();

    const float* gs = (const float*)g_state4;
    int cur = 0;
    #pragma unroll 1
    for (int p = 1; p < PCH; p++) {
        float a0 = 0.f, a1 = 0.f, a2 = 0.f, a3 = 0.f;
        #pragma unroll
        for (int j = 0; j < 32; j++) {
            float4 c4 = cbuf[cur][j];
            a0 += row[j].x * c4.x;  a1 += row[j].y * c4.y;
            a2 += row[j].z * c4.z;  a3 += row[j].w * c4.w;
        }
        float lend = gs[(size_t)(b*LSEQ + p*CL - 1)*NN + n];  // local end of chunk p-1
        float v = (a0 + a1) + (a2 + a3) + lend;
        g_carry[(b*PCH + p)*NN + n] = v;
        ((float*)cbuf[cur ^ 1])[n] = v;
        cur ^= 1;
        __syncthreads();
    }
}

// ---------------- phase C: fixup  S_t += Ad^{k} * carry_p ----------------
__global__ __launch_bounds__(NN, 1) void k_fixup() {
    int b = blockIdx.x >> 6, p = blockIdx.x & 63;
    if (p == 0) return;  // carry_0 = 0, local states already final
    int n = threadIdx.x;
    __shared__ float4 dbuf[2][NN/4];
    float4 row[32];
    #pragma unroll
    for (int j = 0; j < 32; j++) row[j] = g_Ad4v[j*NN + n];
    ((float*)dbuf[0])[n] = g_carry[(b*PCH + p)*NN + n];
    __syncthreads();

    float* gs = (float*)g_state4 + (size_t)(b*LSEQ + p*CL)*NN + n;
    int cur = 0;
    #pragma unroll 1
    for (int i = 0; i < CL; i++) {
        float a0 = 0.f, a1 = 0.f, a2 = 0.f, a3 = 0.f;
        #pragma unroll
        for (int j = 0; j < 32; j++) {
            float4 c4 = dbuf[cur][j];
            a0 += row[j].x * c4.x;  a1 += row[j].y * c4.y;
            a2 += row[j].z * c4.z;  a3 += row[j].w * c4.w;
        }
        float v = (a0 + a1) + (a2 + a3);   // Ad^{i+1} * carry_p
        gs[(size_t)i * NN] += v;
        ((float*)dbuf[cur ^ 1])[n] = v;
        cur ^= 1;
        __syncthreads();
    }
}

// ---------------- phase D: broadcast write  y[b,t,n,k] = C[n]*S + D*f ----
__global__ void k_write(float4* __restrict__ out4,
                        const float* __restrict__ f,
                        const float* __restrict__ Cv,
                        const float* __restrict__ Dv,
                        int yoff4) {
    const long TOTQ = (long)BATCH * LSEQ * NN * (NN/4);  // 16,777,216 float4s
    float D0 = Dv[0];
    long stride = (long)gridDim.x * blockDim.x;
    for (long q = (long)blockIdx.x * blockDim.x + threadIdx.x; q < TOTQ; q += stride) {
        int  k4 = (int)(q & 31);
        int  n  = (int)((q >> 5) & 127);
        long bt = q >> 12;                 // b*LSEQ + t
        float4 s = g_state4[bt*32 + k4];
        float cn = __ldg(Cv + n);
        float dv = D0 * __ldg(f + bt);
        float4 o;
        o.x = fmaf(cn, s.x, dv);  o.y = fmaf(cn, s.y, dv);
        o.z = fmaf(cn, s.z, dv);  o.w = fmaf(cn, s.w, dv);
        __stcs(out4 + yoff4 + q, o);       // streaming store (write-once data)
    }
    // c_final = S[L-1] per batch (first 256 floats of output, if present)
    if (yoff4 >= (BATCH*NN/4) && blockIdx.x == 0 && threadIdx.x < BATCH*NN/4) {
        int t = threadIdx.x;
        int b = t >> 5, k4 = t & 31;
        out4[t] = g_state4[(long)(b*LSEQ + LSEQ - 1)*32 + k4];
    }
}

// ---------------- launcher ----------------
extern "C" void kernel_launch(void* const* d_in, const int* in_sizes, int n_in,
                              void* d_out, int out_size) {
    const float* f  = (const float*)d_in[0];  // (BATCH, L, 1)
    const float* A  = (const float*)d_in[1];  // (N, N)
    const float* Bv = (const float*)d_in[2];  // (N, 1)
    const float* Cv = (const float*)d_in[3];  // (N, 1)
    const float* Dv = (const float*)d_in[4];  // (1,)

    k_transpose<<<NN, NN>>>(A);
    k_solve<<<NN + 1, NN>>>(A, Bv);
    for (int s = 0; s < 5; s++) k_square<<<NN, NN>>>(s);   // Ad^2..Ad^32
    k_local<<<BATCH * PCH, NN>>>(f);
    k_carry<<<BATCH, NN>>>();
    k_fixup<<<BATCH * PCH, NN>>>();

    int ytotal = BATCH * LSEQ * NN * NN;
    int yoff = out_size - ytotal;
    if (yoff < 0) yoff = 0;
    k_write<<<1184, 256>>>((float4*)d_out, f, Cv, Dv, yoff / 4);
}

// round 7
// speedup vs baseline: 2.0223x; 2.0223x over previous
#include <cuda_runtime.h>
#include <cstdint>

#define NN    128
#define BATCH 2
#define LSEQ  2048
#define CL    32
#define PCH   (LSEQ/CL)   // 64 chunks per batch

// ---------------- device scratch (no allocations allowed) ----------------
__device__ float4 g_Ad4v[32*NN];                  // Ad in [m/4][n][4] layout
__device__ float  g_Ad[NN*NN];                    // Ad row-major
__device__ float  g_AT[NN*NN];                    // A transposed
__device__ float  g_Bd[NN];
__device__ float  g_pbuf[2][NN*NN];               // ping-pong for matrix squaring
__device__ float4 g_M324v[32*NN];                 // Ad^32 in [m/4][n][4] layout
__device__ float4 g_state4[BATCH*LSEQ*(NN/4)];    // local states (2 MB, L2-resident)
__device__ float  g_carry[BATCH*PCH*NN];

// ---------------- setup: transpose A ----------------
__global__ void k_transpose(const float* __restrict__ A) {
    int i = blockIdx.x, j = threadIdx.x;
    g_AT[j*NN + i] = A[i*NN + j];
}

// ---------------- setup: GBT discretization via forward substitution -----
// P1 = I - 0.5*A is lower triangular. Block j solves column j of
// P1*Ad = I + 0.5*A (j<128) or P1*Bd = B (j==128). Reciprocal of the
// diagonal is precomputed per thread, so the serial chain has no division.
__global__ __launch_bounds__(NN) void k_solve(const float* __restrict__ A,
                                              const float* __restrict__ Bv) {
    int j = blockIdx.x, i = threadIdx.x;
    __shared__ double sh[2];
    double x;
    if (j < NN) x = (i == j ? 1.0 : 0.0) + 0.5 * (double)A[i*NN + j];
    else        x = (double)Bv[i];
    double rdiag = 1.0 / (1.0 - 0.5 * (double)A[i*NN + i]);  // 1/P1[i][i]

    float at_cur = g_AT[i];  // A[i][0]
    for (int k = 0; k < NN; k++) {
        if (i == k) sh[k & 1] = x * rdiag;
        float at_next = (k < NN-1) ? g_AT[(k+1)*NN + i] : 0.f;
        __syncthreads();
        double xk = sh[k & 1];
        if (i == k)      x = xk;
        else if (i > k)  x = fma(0.5 * (double)at_cur, xk, x);  // x -= P1[i][k]*xk
        at_cur = at_next;
    }
    float xf = (float)x;
    if (j < NN) {
        g_Ad[i*NN + j] = xf;
        ((float*)g_Ad4v)[(j >> 2)*512 + (i << 2) + (j & 3)] = xf;
    } else {
        g_Bd[i] = xf;
    }
}

// ---------------- setup: matrix squaring (Ad^2 ... Ad^32) ----------------
// launch_bounds(128,1): let ptxas use enough registers to batch all loads.
__global__ __launch_bounds__(NN, 1) void k_square(int s) {
    const float* __restrict__ in  = (s == 0) ? g_Ad : g_pbuf[(s-1) & 1];
    float* __restrict__ out = g_pbuf[s & 1];
    int r = blockIdx.x, c = threadIdx.x;
    __shared__ float row[NN];
    row[c] = in[r*NN + c];
    __syncthreads();
    float a[8];
    #pragma unroll
    for (int u = 0; u < 8; u++) a[u] = 0.f;
    #pragma unroll
    for (int m = 0; m < NN; m += 8) {
        #pragma unroll
        for (int u = 0; u < 8; u++)
            a[u] += row[m+u] * in[(m+u)*NN + c];
    }
    float acc = ((a[0]+a[1]) + (a[2]+a[3])) + ((a[4]+a[5]) + (a[6]+a[7]));
    out[r*NN + c] = acc;
    if (s == 4)
        ((float*)g_M324v)[(c >> 2)*512 + (r << 2) + (c & 3)] = acc;
}

// ---------------- phase A: per-chunk local scan from zero state ----------
__global__ __launch_bounds__(NN, 1) void k_local(const float* __restrict__ f) {
    int b = blockIdx.x >> 6, p = blockIdx.x & 63;
    int n = threadIdx.x;
    __shared__ float4 cbuf[2][NN/4];
    __shared__ float  fs[CL];
    float4 row[32];
    #pragma unroll
    for (int j = 0; j < 32; j++) row[j] = g_Ad4v[j*NN + n];
    float bd = g_Bd[n];
    if (n < CL) fs[n] = f[b*LSEQ + p*CL + n];
    ((float*)cbuf[0])[n] = 0.f;
    __syncthreads();

    float* gs = (float*)g_state4 + (size_t)(b*LSEQ + p*CL)*NN + n;
    int cur = 0;
    #pragma unroll 1
    for (int i = 0; i < CL; i++) {
        float a0 = 0.f, a1 = 0.f, a2 = 0.f, a3 = 0.f;
        #pragma unroll
        for (int j = 0; j < 32; j++) {
            float4 c4 = cbuf[cur][j];
            a0 += row[j].x * c4.x;  a1 += row[j].y * c4.y;
            a2 += row[j].z * c4.z;  a3 += row[j].w * c4.w;
        }
        float v = (a0 + a1) + (a2 + a3) + bd * fs[i];
        ((float*)cbuf[cur ^ 1])[n] = v;
        gs[(size_t)i * NN] = v;
        cur ^= 1;
        __syncthreads();
    }
}

// ---------------- phase B: serial carry chain with Ad^32 -----------------
// All 63 chunk-end vectors are prefetched into shared so the serial loop
// has zero exposed global latency.
__global__ __launch_bounds__(NN, 1) void k_carry() {
    int b = blockIdx.x;
    int n = threadIdx.x;
    __shared__ float4 cbuf[2][NN/4];
    __shared__ float  lend_s[(PCH-1)*NN];   // 32 KB
    float4 row[32];
    #pragma unroll
    for (int j = 0; j < 32; j++) row[j] = g_M324v[j*NN + n];

    const float* gs = (const float*)g_state4;
    for (int idx = n; idx < (PCH-1)*NN; idx += NN) {
        int chunk = idx >> 7, col = idx & 127;
        lend_s[idx] = gs[(size_t)(b*LSEQ + (chunk+1)*CL - 1)*NN + col];
    }
    ((float*)cbuf[0])[n] = 0.f;
    g_carry[(b*PCH + 0)*NN + n] = 0.f;
    __syncthreads();

    int cur = 0;
    #pragma unroll 1
    for (int p = 1; p < PCH; p++) {
        float a0 = 0.f, a1 = 0.f, a2 = 0.f, a3 = 0.f;
        #pragma unroll
        for (int j = 0; j < 32; j++) {
            float4 c4 = cbuf[cur][j];
            a0 += row[j].x * c4.x;  a1 += row[j].y * c4.y;
            a2 += row[j].z * c4.z;  a3 += row[j].w * c4.w;
        }
        float v = (a0 + a1) + (a2 + a3) + lend_s[(p-1)*NN + n];
        g_carry[(b*PCH + p)*NN + n] = v;
        ((float*)cbuf[cur ^ 1])[n] = v;
        cur ^= 1;
        __syncthreads();
    }
}

// ---------------- phase C+D fused: fixup + broadcast write + c_final -----
// Threads 0..127: d_{i+1} = Ad*d_i (correction), S_i = local_i + d_{i+1},
// stored to shared (double-buffered). One barrier per step. All 8 warps
// then stream-write y[b,t,n,:] rows: warp w owns rows [16w,16w+16), each
// STG.128 writes one full 512B row (coalesced).
__global__ __launch_bounds__(256) void k_out(float4* __restrict__ out4,
                                             const float* __restrict__ f,
                                             const float* __restrict__ Cv,
                                             const float* __restrict__ Dv,
                                             int yoff4) {
    int b = blockIdx.x >> 6, p = blockIdx.x & 63;
    int tid = threadIdx.x;
    int w = tid >> 5, lane = tid & 31;
    __shared__ float4 dbuf[2][NN/4];
    __shared__ float4 sbuf[2][NN/4];
    __shared__ float  fs[CL];

    float4 row[32];
    if (p > 0 && tid < NN) {
        #pragma unroll
        for (int j = 0; j < 32; j++) row[j] = g_Ad4v[j*NN + tid];
    }
    if (tid < NN) ((float*)dbuf[1])[tid] = (p > 0) ? g_carry[(b*PCH + p)*NN + tid] : 0.f;
    if (tid < CL) fs[tid] = f[b*LSEQ + p*CL + tid];

    float creg[16];
    #pragma unroll
    for (int r2 = 0; r2 < 16; r2++) creg[r2] = Cv[w*16 + r2];
    float D0 = Dv[0];

    const float* gs = (const float*)g_state4 + (size_t)(b*LSEQ + p*CL)*NN;
    float4* yout = out4 + yoff4 + (size_t)(b*LSEQ + p*CL)*NN*(NN/4);

    float gnext = (tid < NN) ? gs[tid] : 0.f;   // prefetch local state, step 0
    __syncthreads();

    #pragma unroll 1
    for (int i = 0; i < CL; i++) {
        int cw = i & 1;          // buffer written this step
        int cr = cw ^ 1;         // d buffer read this step
        if (tid < NN) {
            float gcur = gnext;
            if (i < CL-1) gnext = gs[(size_t)(i+1)*NN + tid];
            float v;
            if (p > 0) {
                float a0 = 0.f, a1 = 0.f, a2 = 0.f, a3 = 0.f;
                #pragma unroll
                for (int j = 0; j < 32; j++) {
                    float4 c4 = dbuf[cr][j];
                    a0 += row[j].x * c4.x;  a1 += row[j].y * c4.y;
                    a2 += row[j].z * c4.z;  a3 += row[j].w * c4.w;
                }
                float d = (a0 + a1) + (a2 + a3);
                ((float*)dbuf[cw])[tid] = d;
                v = gcur + d;
            } else {
                v = gcur;
            }
            ((float*)sbuf[cw])[tid] = v;
        }
        __syncthreads();
        // write phase: all 256 threads
        float4 s4 = sbuf[cw][lane];
        float df = D0 * fs[i];
        float4* yrow = yout + (size_t)i*NN*(NN/4) + w*16*(NN/4) + lane;
        #pragma unroll
        for (int r2 = 0; r2 < 16; r2++) {
            float cn = creg[r2];
            float4 o;
            o.x = fmaf(cn, s4.x, df);  o.y = fmaf(cn, s4.y, df);
            o.z = fmaf(cn, s4.z, df);  o.w = fmaf(cn, s4.w, df);
            __stcs(yrow + (size_t)r2*(NN/4), o);
        }
    }

    // c_final: last chunk's block writes S[L-1] (sits in sbuf[(CL-1)&1])
    if (p == PCH-1 && yoff4 >= (BATCH*NN/4) && tid < NN/4) {
        out4[b*(NN/4) + tid] = sbuf[(CL-1) & 1][tid];
    }
}

// ---------------- launcher ----------------
extern "C" void kernel_launch(void* const* d_in, const int* in_sizes, int n_in,
                              void* d_out, int out_size) {
    const float* f  = (const float*)d_in[0];  // (BATCH, L, 1)
    const float* A  = (const float*)d_in[1];  // (N, N)
    const float* Bv = (const float*)d_in[2];  // (N, 1)
    const float* Cv = (const float*)d_in[3];  // (N, 1)
    const float* Dv = (const float*)d_in[4];  // (1,)

    k_transpose<<<NN, NN>>>(A);
    k_solve<<<NN + 1, NN>>>(A, Bv);
    for (int s = 0; s < 5; s++) k_square<<<NN, NN>>>(s);   // Ad^2..Ad^32
    k_local<<<BATCH * PCH, NN>>>(f);
    k_carry<<<BATCH, NN>>>();

    int ytotal = BATCH * LSEQ * NN * NN;
    int yoff = out_size - ytotal;
    if (yoff < 0) yoff = 0;
    k_out<<<BATCH * PCH, 256>>>((float4*)d_out, f, Cv, Dv, yoff / 4);
}

// round 8
// speedup vs baseline: 2.0251x; 1.0014x over previous
#include <cuda_runtime.h>
#include <cstdint>

#define NN    128
#define BATCH 2
#define LSEQ  2048
#define CL    32
#define PCH   (LSEQ/CL)   // 64 chunks per batch

// ---------------- device scratch (no allocations allowed) ----------------
__device__ float4 g_Ad4v[32*NN];                  // Ad in [m/4][n][4] layout
__device__ float  g_Ad[NN*NN];                    // Ad row-major
__device__ float  g_AT[NN*NN];                    // A transposed
__device__ float  g_Bd[NN];
__device__ float  g_pbuf[2][NN*NN];               // ping-pong for matrix squaring
__device__ float4 g_M324v[32*NN];                 // Ad^32 in [m/4][n][4] layout
__device__ float  g_lend[BATCH*PCH*NN];           // chunk-end local states (64 KB)
__device__ float  g_carry[BATCH*PCH*NN];

// ---------------- setup: transpose A ----------------
__global__ void k_transpose(const float* __restrict__ A) {
    int i = blockIdx.x, j = threadIdx.x;
    g_AT[j*NN + i] = A[i*NN + j];
}

// ---------------- setup: GBT discretization via forward substitution -----
// P1 = I - 0.5*A is lower triangular. Block j solves column j of
// P1*Ad = I + 0.5*A (j<128) or P1*Bd = B (j==128).
__global__ __launch_bounds__(NN) void k_solve(const float* __restrict__ A,
                                              const float* __restrict__ Bv) {
    int j = blockIdx.x, i = threadIdx.x;
    __shared__ double sh[2];
    double x;
    if (j < NN) x = (i == j ? 1.0 : 0.0) + 0.5 * (double)A[i*NN + j];
    else        x = (double)Bv[i];
    double rdiag = 1.0 / (1.0 - 0.5 * (double)A[i*NN + i]);  // 1/P1[i][i]

    float at_cur = g_AT[i];  // A[i][0]
    for (int k = 0; k < NN; k++) {
        if (i == k) sh[k & 1] = x * rdiag;
        float at_next = (k < NN-1) ? g_AT[(k+1)*NN + i] : 0.f;
        __syncthreads();
        double xk = sh[k & 1];
        if (i == k)      x = xk;
        else if (i > k)  x = fma(0.5 * (double)at_cur, xk, x);  // x -= P1[i][k]*xk
        at_cur = at_next;
    }
    float xf = (float)x;
    if (j < NN) {
        g_Ad[i*NN + j] = xf;
        ((float*)g_Ad4v)[(j >> 2)*512 + (i << 2) + (j & 3)] = xf;
    } else {
        g_Bd[i] = xf;
    }
}

// ---------------- setup: matrix squaring (Ad^2 ... Ad^32) ----------------
// 512 threads/block: 4 m-segments per column -> per-thread L2 load chain is
// 32 (not 128); shared reduction combines the partials.
__global__ __launch_bounds__(512, 1) void k_square(int s) {
    const float* __restrict__ in  = (s == 0) ? g_Ad : g_pbuf[(s-1) & 1];
    float* __restrict__ out = g_pbuf[s & 1];
    int r = blockIdx.x;
    int c = threadIdx.x & 127, seg = threadIdx.x >> 7;
    __shared__ float row[NN];
    __shared__ float part[3][NN];
    if (threadIdx.x < NN) row[threadIdx.x] = in[r*NN + threadIdx.x];
    __syncthreads();
    int base = seg * 32;
    float a[4];
    #pragma unroll
    for (int u = 0; u < 4; u++) a[u] = 0.f;
    #pragma unroll
    for (int m = 0; m < 32; m += 4) {
        #pragma unroll
        for (int u = 0; u < 4; u++)
            a[u] += row[base + m + u] * in[(base + m + u)*NN + c];
    }
    float acc = (a[0] + a[1]) + (a[2] + a[3]);
    if (seg > 0) part[seg-1][c] = acc;
    __syncthreads();
    if (seg == 0) {
        acc += (part[0][c] + part[1][c]) + part[2][c];
        out[r*NN + c] = acc;
        if (s == 4)
            ((float*)g_M324v)[(c >> 2)*512 + (r << 2) + (c & 3)] = acc;
    }
}

// ---------------- phase A: per-chunk local scan, emit chunk-end only -----
__global__ __launch_bounds__(NN, 1) void k_local(const float* __restrict__ f) {
    int b = blockIdx.x >> 6, p = blockIdx.x & 63;
    int n = threadIdx.x;
    __shared__ float4 cbuf[2][NN/4];
    __shared__ float  fs[CL];
    float4 row[32];
    #pragma unroll
    for (int j = 0; j < 32; j++) row[j] = g_Ad4v[j*NN + n];
    float bd = g_Bd[n];
    if (n < CL) fs[n] = f[b*LSEQ + p*CL + n];
    ((float*)cbuf[0])[n] = 0.f;
    __syncthreads();

    int cur = 0;
    float v = 0.f;
    #pragma unroll 1
    for (int i = 0; i < CL; i++) {
        float a0 = 0.f, a1 = 0.f, a2 = 0.f, a3 = 0.f;
        #pragma unroll
        for (int j = 0; j < 32; j++) {
            float4 c4 = cbuf[cur][j];
            a0 += row[j].x * c4.x;  a1 += row[j].y * c4.y;
            a2 += row[j].z * c4.z;  a3 += row[j].w * c4.w;
        }
        v = (a0 + a1) + (a2 + a3) + bd * fs[i];
        ((float*)cbuf[cur ^ 1])[n] = v;
        cur ^= 1;
        __syncthreads();
    }
    g_lend[(b*PCH + p)*NN + n] = v;   // chunk-end state (contiguous for k_carry)
}

// ---------------- phase B: serial carry chain with Ad^32 -----------------
// carry_0 = 0 ; carry_p = Ad^32 * carry_{p-1} + lend_{p-1}
__global__ __launch_bounds__(NN, 1) void k_carry() {
    int b = blockIdx.x;
    int n = threadIdx.x;
    __shared__ float4 cbuf[2][NN/4];
    __shared__ float  lend_s[(PCH-1)*NN];   // 32 KB, fully coalesced prefetch
    float4 row[32];
    #pragma unroll
    for (int j = 0; j < 32; j++) row[j] = g_M324v[j*NN + n];

    for (int idx = n; idx < (PCH-1)*NN; idx += NN)
        lend_s[idx] = g_lend[b*PCH*NN + idx];
    ((float*)cbuf[0])[n] = 0.f;
    g_carry[(b*PCH + 0)*NN + n] = 0.f;
    __syncthreads();

    int cur = 0;
    #pragma unroll 1
    for (int p = 1; p < PCH; p++) {
        float a0 = 0.f, a1 = 0.f, a2 = 0.f, a3 = 0.f;
        #pragma unroll
        for (int j = 0; j < 32; j++) {
            float4 c4 = cbuf[cur][j];
            a0 += row[j].x * c4.x;  a1 += row[j].y * c4.y;
            a2 += row[j].z * c4.z;  a3 += row[j].w * c4.w;
        }
        float v = (a0 + a1) + (a2 + a3) + lend_s[(p-1)*NN + n];
        g_carry[(b*PCH + p)*NN + n] = v;
        ((float*)cbuf[cur ^ 1])[n] = v;
        cur ^= 1;
        __syncthreads();
    }
}

// ---------------- phase C: seeded rescan + broadcast write + c_final -----
// Grid = 256: blocks (p,h) re-run the chunk recurrence seeded with carry_p
// (identical math to local+fixup) and write the N-row half h of every
// y[b,t,:,:] tile. Threads 0..127 compute; all 8 warps stream STG.128 rows.
__global__ __launch_bounds__(256, 1) void k_out(float4* __restrict__ out4,
                                                const float* __restrict__ f,
                                                const float* __restrict__ Cv,
                                                const float* __restrict__ Dv,
                                                int yoff4) {
    int bidx = blockIdx.x;
    int b = bidx >> 7, ph = bidx & 127;
    int p = ph >> 1, h = ph & 1;
    int tid = threadIdx.x;
    int w = tid >> 5, lane = tid & 31;
    __shared__ float4 sbuf[2][NN/4];
    __shared__ float  fs[CL];

    float4 row[32];
    if (tid < NN) {
        #pragma unroll
        for (int j = 0; j < 32; j++) row[j] = g_Ad4v[j*NN + tid];
    }
    float bd = (tid < NN) ? g_Bd[tid] : 0.f;
    if (tid < NN) ((float*)sbuf[1])[tid] = g_carry[(b*PCH + p)*NN + tid];  // seed
    if (tid < CL) fs[tid] = f[b*LSEQ + p*CL + tid];

    float creg[8];
    #pragma unroll
    for (int r2 = 0; r2 < 8; r2++) creg[r2] = Cv[h*64 + w*8 + r2];
    float D0 = Dv[0];

    float4* yout = out4 + yoff4 + (size_t)(b*LSEQ + p*CL)*NN*(NN/4);
    __syncthreads();

    #pragma unroll 1
    for (int i = 0; i < CL; i++) {
        int cw = i & 1;          // buffer written this step
        int cr = cw ^ 1;         // previous state buffer
        if (tid < NN) {
            float a0 = 0.f, a1 = 0.f, a2 = 0.f, a3 = 0.f;
            #pragma unroll
            for (int j = 0; j < 32; j++) {
                float4 c4 = sbuf[cr][j];
                a0 += row[j].x * c4.x;  a1 += row[j].y * c4.y;
                a2 += row[j].z * c4.z;  a3 += row[j].w * c4.w;
            }
            ((float*)sbuf[cw])[tid] = (a0 + a1) + (a2 + a3) + bd * fs[i];
        }
        __syncthreads();
        float4 s4 = sbuf[cw][lane];
        float df = D0 * fs[i];
        float4* yrow = yout + (size_t)i*NN*(NN/4) + (h*64 + w*8)*(NN/4) + lane;
        #pragma unroll
        for (int r2 = 0; r2 < 8; r2++) {
            float cn = creg[r2];
            float4 o;
            o.x = fmaf(cn, s4.x, df);  o.y = fmaf(cn, s4.y, df);
            o.z = fmaf(cn, s4.z, df);  o.w = fmaf(cn, s4.w, df);
            __stcs(yrow + (size_t)r2*(NN/4), o);
        }
    }

    // c_final: last chunk, h==0 block writes S[L-1] (in sbuf[(CL-1)&1])
    if (p == PCH-1 && h == 0 && yoff4 >= (BATCH*NN/4) && tid < NN/4) {
        out4[b*(NN/4) + tid] = sbuf[(CL-1) & 1][tid];
    }
}

// ---------------- launcher ----------------
extern "C" void kernel_launch(void* const* d_in, const int* in_sizes, int n_in,
                              void* d_out, int out_size) {
    const float* f  = (const float*)d_in[0];  // (BATCH, L, 1)
    const float* A  = (const float*)d_in[1];  // (N, N)
    const float* Bv = (const float*)d_in[2];  // (N, 1)
    const float* Cv = (const float*)d_in[3];  // (N, 1)
    const float* Dv = (const float*)d_in[4];  // (1,)

    k_transpose<<<NN, NN>>>(A);
    k_solve<<<NN + 1, NN>>>(A, Bv);
    for (int s = 0; s < 5; s++) k_square<<<NN, 512>>>(s);   // Ad^2..Ad^32
    k_local<<<BATCH * PCH, NN>>>(f);
    k_carry<<<BATCH, NN>>>();

    int ytotal = BATCH * LSEQ * NN * NN;
    int yoff = out_size - ytotal;
    if (yoff < 0) yoff = 0;
    k_out<<<2 * BATCH * PCH, 256>>>((float4*)d_out, f, Cv, Dv, yoff / 4);
}

// round 9
// speedup vs baseline: 2.2648x; 1.1184x over previous
#include <cuda_runtime.h>
#include <cstdint>

#define NN    128
#define BATCH 2
#define LSEQ  2048
#define CL    32
#define PCH   (LSEQ/CL)   // 64 chunks per batch

typedef unsigned long long u64;

// packed f32x2 FMA (sm_103a FFMA2): d.lo += a.lo*b.lo ; d.hi += a.hi*b.hi
__device__ __forceinline__ void ffma2(u64& d, u64 a, u64 b) {
    asm("fma.rn.f32x2 %0, %1, %2, %0;" : "+l"(d) : "l"(a), "l"(b));
}
__device__ __forceinline__ float f2lo(u64 a){ return __int_as_float((int)(unsigned)(a & 0xffffffffull)); }
__device__ __forceinline__ float f2hi(u64 a){ return __int_as_float((int)(unsigned)(a >> 32)); }

// ---------------- device scratch (no allocations allowed) ----------------
// Ad packed: double2 element [m*NN+n] holds Ad[n][4m..4m+3] as 4 floats.
__device__ double2 g_Ad2[32*NN];
__device__ double2 g_M32[32*NN];                  // Ad^32, same layout
__device__ float   g_Bd[NN];
__device__ float   g_lend[BATCH*PCH*NN];          // chunk-end local states
__device__ float   g_carry[BATCH*PCH*NN];

// ---------------- setup: GBT discretization (transpose fused) ------------
// P1 = I - 0.5*A is lower triangular (HiPPO-LegS). Block j solves column j
// of P1*Ad = I + 0.5*A (j<128) or P1*Bd = B (j==128), forward substitution
// in fp64. Only the lower triangle of A is ever read -> packed 33KB shared
// copy, filled coalesced (kills the separate transpose kernel).
// Division-free chain: thread i maintains y = x * (1/P1[i][i]); published
// sh value IS the solution element.
__global__ __launch_bounds__(NN) void k_solve(const float* __restrict__ A,
                                              const float* __restrict__ Bv) {
    int j = blockIdx.x, i = threadIdx.x;
    __shared__ float AT_s[NN*(NN+1)/2 + 1];   // packed lower triangle (+1 pad)
    __shared__ double sh[2];

    for (int idx = i; idx < NN*NN; idx += NN) {
        int r = idx >> 7, c = idx & 127;
        if (c <= r) AT_s[r*(r+1)/2 + c] = A[idx];
    }
    __syncthreads();

    int tri_i = i*(i+1)/2;
    double rdiag = 1.0 / (1.0 - 0.5 * (double)AT_s[tri_i + i]);
    double hrd   = 0.5 * rdiag;

    double rhs;
    if (j < NN) rhs = (i == j ? 1.0 : 0.0) + 0.5 * (double)A[i*NN + j];
    else        rhs = (double)Bv[i];
    double y = rhs * rdiag;

    float at = AT_s[tri_i];   // A[i][0] (valid for i>=0)
    #pragma unroll 4
    for (int k = 0; k < NN; k++) {
        double coef = hrd * (double)at;     // off critical path
        if (i == k) sh[k & 1] = y;
        at = AT_s[tri_i + k + 1];           // prefetch next (pad covers k=127)
        __syncthreads();
        double xk = sh[k & 1];
        if (i > k) y = fma(coef, xk, y);
    }

    float xf = (float)y;
    if (j < NN) ((float*)g_Ad2)[(j >> 2)*512 + (i << 2) + (j & 3)] = xf;
    else        g_Bd[i] = xf;
}

// ---------------- phase A: local scans + Ad^32 columns (one launch) ------
// Blocks [0,128): chunk-local scan, emits chunk-end state only.
// Blocks [128,256): column (bid-128) of Ad^32 via 32 iterated matvecs.
__global__ __launch_bounds__(NN, 1) void k_local32(const float* __restrict__ f) {
    int bid = blockIdx.x;
    int n = threadIdx.x;
    __shared__ double2 cbuf[2][32];
    __shared__ float   fs[CL];

    u64 rl[32], rh[32];
    #pragma unroll
    for (int j = 0; j < 32; j++) {
        double2 t = g_Ad2[j*NN + n];
        rl[j] = __double_as_longlong(t.x);
        rh[j] = __double_as_longlong(t.y);
    }

    bool ispow = (bid >= BATCH*PCH);
    int b = 0, p = 0, jcol = 0;
    float bd = 0.f;
    if (!ispow) {
        b = bid >> 6; p = bid & 63;
        bd = g_Bd[n];
        if (n < CL) fs[n] = f[b*LSEQ + p*CL + n];
        ((float*)cbuf[0])[n] = 0.f;
    } else {
        jcol = bid - BATCH*PCH;
        ((float*)cbuf[0])[n] = (n == jcol) ? 1.f : 0.f;
    }
    __syncthreads();

    int cur = 0;
    float v = 0.f;
    #pragma unroll 1
    for (int i = 0; i < CL; i++) {
        u64 a0 = 0, a1 = 0, a2 = 0, a3 = 0;
        #pragma unroll
        for (int j = 0; j < 32; j += 2) {
            double2 c0 = cbuf[cur][j];
            double2 c1 = cbuf[cur][j+1];
            ffma2(a0, rl[j],   __double_as_longlong(c0.x));
            ffma2(a1, rh[j],   __double_as_longlong(c0.y));
            ffma2(a2, rl[j+1], __double_as_longlong(c1.x));
            ffma2(a3, rh[j+1], __double_as_longlong(c1.y));
        }
        v = ((f2lo(a0)+f2hi(a0)) + (f2lo(a1)+f2hi(a1)))
          + ((f2lo(a2)+f2hi(a2)) + (f2lo(a3)+f2hi(a3)));
        if (!ispow) v += bd * fs[i];
        ((float*)cbuf[cur ^ 1])[n] = v;
        cur ^= 1;
        __syncthreads();
    }

    if (!ispow) g_lend[(bid)*NN + n] = v;                                    // contiguous
    else        ((float*)g_M32)[(jcol >> 2)*512 + (n << 2) + (jcol & 3)] = v; // M32[n][jcol]
}

// ---------------- phase B: serial carry chain with Ad^32 -----------------
// carry_0 = 0 ; carry_p = Ad^32 * carry_{p-1} + lend_{p-1}
__global__ __launch_bounds__(NN, 1) void k_carry() {
    int b = blockIdx.x;
    int n = threadIdx.x;
    __shared__ double2 cbuf[2][32];
    __shared__ float   lend_s[(PCH-1)*NN];   // 32 KB, coalesced prefetch
    u64 rl[32], rh[32];
    #pragma unroll
    for (int j = 0; j < 32; j++) {
        double2 t = g_M32[j*NN + n];
        rl[j] = __double_as_longlong(t.x);
        rh[j] = __double_as_longlong(t.y);
    }
    for (int idx = n; idx < (PCH-1)*NN; idx += NN)
        lend_s[idx] = g_lend[b*PCH*NN + idx];
    ((float*)cbuf[0])[n] = 0.f;
    g_carry[(b*PCH + 0)*NN + n] = 0.f;
    __syncthreads();

    int cur = 0;
    #pragma unroll 1
    for (int p = 1; p < PCH; p++) {
        u64 a0 = 0, a1 = 0, a2 = 0, a3 = 0;
        #pragma unroll
        for (int j = 0; j < 32; j += 2) {
            double2 c0 = cbuf[cur][j];
            double2 c1 = cbuf[cur][j+1];
            ffma2(a0, rl[j],   __double_as_longlong(c0.x));
            ffma2(a1, rh[j],   __double_as_longlong(c0.y));
            ffma2(a2, rl[j+1], __double_as_longlong(c1.x));
            ffma2(a3, rh[j+1], __double_as_longlong(c1.y));
        }
        float v = ((f2lo(a0)+f2hi(a0)) + (f2lo(a1)+f2hi(a1)))
                + ((f2lo(a2)+f2hi(a2)) + (f2lo(a3)+f2hi(a3)))
                + lend_s[(p-1)*NN + n];
        g_carry[(b*PCH + p)*NN + n] = v;
        ((float*)cbuf[cur ^ 1])[n] = v;
        cur ^= 1;
        __syncthreads();
    }
}

// ---------------- phase C: seeded rescan + broadcast write + c_final -----
// Blocks (b,p,h): re-run chunk recurrence seeded with carry_p (math identical
// to local+fixup) and write N-row half h of every y[b,t,:,:] tile.
// Threads 0..127 compute; all 8 warps stream STG.128 full 512B rows.
__global__ __launch_bounds__(256, 1) void k_out(float4* __restrict__ out4,
                                                const float* __restrict__ f,
                                                const float* __restrict__ Cv,
                                                const float* __restrict__ Dv,
                                                int yoff4) {
    int bidx = blockIdx.x;
    int b = bidx >> 7, ph = bidx & 127;
    int p = ph >> 1, h = ph & 1;
    int tid = threadIdx.x;
    int w = tid >> 5, lane = tid & 31;
    __shared__ double2 sbuf[2][32];
    __shared__ float   fs[CL];

    u64 rl[32], rh[32];
    float bd = 0.f;
    if (tid < NN) {
        #pragma unroll
        for (int j = 0; j < 32; j++) {
            double2 t = g_Ad2[j*NN + tid];
            rl[j] = __double_as_longlong(t.x);
            rh[j] = __double_as_longlong(t.y);
        }
        bd = g_Bd[tid];
        ((float*)sbuf[1])[tid] = g_carry[(b*PCH + p)*NN + tid];  // seed
    }
    if (tid < CL) fs[tid] = f[b*LSEQ + p*CL + tid];

    float creg[8];
    #pragma unroll
    for (int r2 = 0; r2 < 8; r2++) creg[r2] = Cv[h*64 + w*8 + r2];
    float D0 = Dv[0];

    float4* yout = out4 + yoff4 + (size_t)(b*LSEQ + p*CL)*NN*(NN/4);
    __syncthreads();

    #pragma unroll 1
    for (int i = 0; i < CL; i++) {
        int cw = i & 1;          // buffer written this step
        int cr = cw ^ 1;         // previous state buffer
        if (tid < NN) {
            u64 a0 = 0, a1 = 0, a2 = 0, a3 = 0;
            #pragma unroll
            for (int j = 0; j < 32; j += 2) {
                double2 c0 = sbuf[cr][j];
                double2 c1 = sbuf[cr][j+1];
                ffma2(a0, rl[j],   __double_as_longlong(c0.x));
                ffma2(a1, rh[j],   __double_as_longlong(c0.y));
                ffma2(a2, rl[j+1], __double_as_longlong(c1.x));
                ffma2(a3, rh[j+1], __double_as_longlong(c1.y));
            }
            float v = ((f2lo(a0)+f2hi(a0)) + (f2lo(a1)+f2hi(a1)))
                    + ((f2lo(a2)+f2hi(a2)) + (f2lo(a3)+f2hi(a3)))
                    + bd * fs[i];
            ((float*)sbuf[cw])[tid] = v;
        }
        __syncthreads();
        float4 s4 = ((float4*)sbuf[cw])[lane];
        float df = D0 * fs[i];
        float4* yrow = yout + (size_t)i*NN*(NN/4) + (h*64 + w*8)*(NN/4) + lane;
        #pragma unroll
        for (int r2 = 0; r2 < 8; r2++) {
            float cn = creg[r2];
            float4 o;
            o.x = fmaf(cn, s4.x, df);  o.y = fmaf(cn, s4.y, df);
            o.z = fmaf(cn, s4.z, df);  o.w = fmaf(cn, s4.w, df);
            __stcs(yrow + (size_t)r2*(NN/4), o);
        }
    }

    // c_final: last chunk, h==0 block writes S[L-1] (in sbuf[(CL-1)&1])
    if (p == PCH-1 && h == 0 && yoff4 >= (BATCH*NN/4) && tid < NN/4) {
        out4[b*(NN/4) + tid] = ((float4*)sbuf[(CL-1) & 1])[tid];
    }
}

// ---------------- launcher ----------------
extern "C" void kernel_launch(void* const* d_in, const int* in_sizes, int n_in,
                              void* d_out, int out_size) {
    const float* f  = (const float*)d_in[0];  // (BATCH, L, 1)
    const float* A  = (const float*)d_in[1];  // (N, N)
    const float* Bv = (const float*)d_in[2];  // (N, 1)
    const float* Cv = (const float*)d_in[3];  // (N, 1)
    const float* Dv = (const float*)d_in[4];  // (1,)

    k_solve<<<NN + 1, NN>>>(A, Bv);
    k_local32<<<BATCH*PCH + NN, NN>>>(f);
    k_carry<<<BATCH, NN>>>();

    int ytotal = BATCH * LSEQ * NN * NN;
    int yoff = out_size - ytotal;
    if (yoff < 0) yoff = 0;
    k_out<<<2 * BATCH * PCH, 256>>>((float4*)d_out, f, Cv, Dv, yoff / 4);
}